// round 1
// baseline (speedup 1.0000x reference)
#include <cuda_runtime.h>
#include <math.h>

// Fixed problem shape
#define BATCH 4
#define SEQ   2048
#define DMODEL 1024
#define NHEAD 16
#define HD    64
#define MM (BATCH*SEQ)     // 8192
#define KK DMODEL          // 1024
#define NN DMODEL          // 1024

// Scratch (allocation-free: __device__ globals)
__device__ float g_Q[MM*NN];
__device__ float g_K[MM*NN];
__device__ float g_V[MM*NN];
__device__ float g_AO[MM*NN];

// ---------------------------------------------------------------------------
// SGEMM: C[M,N] = A[M,K] @ B[K,N] (+ bias). Fixed M=8192,K=1024,N=1024.
// 128x128 block tile, BK=16, 256 threads, 8x8 per-thread microtile.
// ---------------------------------------------------------------------------
__global__ __launch_bounds__(256) void sgemm_kernel(
    const float* __restrict__ A, const float* __restrict__ B,
    float* __restrict__ C, const float* __restrict__ bias)
{
    __shared__ float As[16][132];   // transposed A tile: As[k][m]
    __shared__ float Bs[16][132];   // Bs[k][n]

    const int tid = threadIdx.x;
    const int tx = tid & 15;
    const int ty = tid >> 4;
    const int m0 = blockIdx.y * 128;
    const int n0 = blockIdx.x * 128;

    float acc[8][8];
#pragma unroll
    for (int i = 0; i < 8; i++)
#pragma unroll
        for (int j = 0; j < 8; j++) acc[i][j] = 0.0f;

    const int a_row = tid >> 2;          // 0..63
    const int a_col = (tid & 3) << 2;    // 0,4,8,12
    const int b_row = tid >> 5;          // 0..7
    const int b_col = (tid & 31) << 2;   // 0..124

    for (int k0 = 0; k0 < KK; k0 += 16) {
#pragma unroll
        for (int r = 0; r < 2; r++) {
            int row = a_row + r * 64;
            float4 v = *(const float4*)(A + (size_t)(m0 + row) * KK + k0 + a_col);
            As[a_col + 0][row] = v.x;
            As[a_col + 1][row] = v.y;
            As[a_col + 2][row] = v.z;
            As[a_col + 3][row] = v.w;
        }
#pragma unroll
        for (int r = 0; r < 2; r++) {
            int row = b_row + r * 8;
            *(float4*)(&Bs[row][b_col]) =
                *(const float4*)(B + (size_t)(k0 + row) * NN + n0 + b_col);
        }
        __syncthreads();

#pragma unroll
        for (int k = 0; k < 16; k++) {
            float ra[8], rb[8];
            *(float4*)(ra)     = *(float4*)(&As[k][ty * 8]);
            *(float4*)(ra + 4) = *(float4*)(&As[k][ty * 8 + 4]);
            *(float4*)(rb)     = *(float4*)(&Bs[k][tx * 8]);
            *(float4*)(rb + 4) = *(float4*)(&Bs[k][tx * 8 + 4]);
#pragma unroll
            for (int i = 0; i < 8; i++)
#pragma unroll
                for (int j = 0; j < 8; j++)
                    acc[i][j] += ra[i] * rb[j];
        }
        __syncthreads();
    }

#pragma unroll
    for (int i = 0; i < 8; i++) {
        int row = m0 + ty * 8 + i;
#pragma unroll
        for (int j4 = 0; j4 < 8; j4 += 4) {
            float4 v;
            v.x = acc[i][j4 + 0];
            v.y = acc[i][j4 + 1];
            v.z = acc[i][j4 + 2];
            v.w = acc[i][j4 + 3];
            if (bias) {
                float4 bvec = *(const float4*)(bias + n0 + tx * 8 + j4);
                v.x += bvec.x; v.y += bvec.y; v.z += bvec.z; v.w += bvec.w;
            }
            *(float4*)(C + (size_t)row * NN + n0 + tx * 8 + j4) = v;
        }
    }
}

// ---------------------------------------------------------------------------
// Flash attention (causal), fp32. BM=BN=64, d=64.
// grid: (SEQ/64, BATCH*NHEAD), 256 threads (16x16; each thread: 4x4 tiles).
// Smem (dynamic): Qt[d][m] , Kt[d][n] , Vs[n][d] , Pt[n][m]; all stride 68.
// ---------------------------------------------------------------------------
#define FSTR 68
#define FLASH_SMEM (4 * 64 * FSTR * 4)

__global__ __launch_bounds__(256) void flash_kernel(
    const float* __restrict__ Q, const float* __restrict__ K,
    const float* __restrict__ V, float* __restrict__ O)
{
    extern __shared__ float sm[];
    float* Qt = sm;
    float* Kt = sm + 1 * 64 * FSTR;
    float* Vs = sm + 2 * 64 * FSTR;
    float* Pt = sm + 3 * 64 * FSTR;

    const int tid = threadIdx.x;
    const int tx = tid & 15;
    const int ty = tid >> 4;
    const int ib = blockIdx.x;
    const int bh = blockIdx.y;
    const int b = bh >> 4;
    const int head = bh & 15;
    const size_t base = (size_t)b * SEQ * DMODEL + (size_t)head * HD;
    const int i0 = ib * 64;

    // load Q tile transposed, fold in 1/sqrt(hd)=0.125
    {
        const int lrow = tid >> 4;         // 0..15
        const int lcol = (tid & 15) << 2;  // 0..60
#pragma unroll
        for (int p = 0; p < 4; p++) {
            int row = lrow + p * 16;
            float4 v = *(const float4*)(Q + base + (size_t)(i0 + row) * DMODEL + lcol);
            Qt[(lcol + 0) * FSTR + row] = v.x * 0.125f;
            Qt[(lcol + 1) * FSTR + row] = v.y * 0.125f;
            Qt[(lcol + 2) * FSTR + row] = v.z * 0.125f;
            Qt[(lcol + 3) * FSTR + row] = v.w * 0.125f;
        }
    }

    float o[4][4];
#pragma unroll
    for (int i = 0; i < 4; i++)
#pragma unroll
        for (int j = 0; j < 4; j++) o[i][j] = 0.0f;
    float mi[4] = {-1e30f, -1e30f, -1e30f, -1e30f};
    float li[4] = {0.f, 0.f, 0.f, 0.f};

    for (int jb = 0; jb <= ib; jb++) {
        const int j0 = jb * 64;
        // load K (transposed) and V (direct) tiles
        {
            const int lrow = tid >> 4;
            const int lcol = (tid & 15) << 2;
#pragma unroll
            for (int p = 0; p < 4; p++) {
                int row = lrow + p * 16;
                float4 kv = *(const float4*)(K + base + (size_t)(j0 + row) * DMODEL + lcol);
                Kt[(lcol + 0) * FSTR + row] = kv.x;
                Kt[(lcol + 1) * FSTR + row] = kv.y;
                Kt[(lcol + 2) * FSTR + row] = kv.z;
                Kt[(lcol + 3) * FSTR + row] = kv.w;
                float4 vv = *(const float4*)(V + base + (size_t)(j0 + row) * DMODEL + lcol);
                *(float4*)(Vs + (size_t)row * FSTR + lcol) = vv;
            }
        }
        __syncthreads();

        // S = (Q*0.125) @ K^T   (4x4 per thread)
        float s[4][4];
#pragma unroll
        for (int i = 0; i < 4; i++)
#pragma unroll
            for (int j = 0; j < 4; j++) s[i][j] = 0.0f;

#pragma unroll 8
        for (int d = 0; d < 64; d++) {
            float qa[4], kb[4];
            *(float4*)qa = *(float4*)(Qt + d * FSTR + (ty << 2));
            *(float4*)kb = *(float4*)(Kt + d * FSTR + (tx << 2));
#pragma unroll
            for (int i = 0; i < 4; i++)
#pragma unroll
                for (int j = 0; j < 4; j++)
                    s[i][j] += qa[i] * kb[j];
        }

        // causal mask on diagonal block
        if (jb == ib) {
#pragma unroll
            for (int i = 0; i < 4; i++)
#pragma unroll
                for (int j = 0; j < 4; j++)
                    if (((tx << 2) + j) > ((ty << 2) + i)) s[i][j] = -1e30f;
        }

        // online softmax (per row; 16 lanes share a row -> shfl reduce)
#pragma unroll
        for (int i = 0; i < 4; i++) {
            float rm = s[i][0];
            rm = fmaxf(rm, s[i][1]);
            rm = fmaxf(rm, s[i][2]);
            rm = fmaxf(rm, s[i][3]);
            rm = fmaxf(rm, __shfl_xor_sync(0xffffffffu, rm, 1));
            rm = fmaxf(rm, __shfl_xor_sync(0xffffffffu, rm, 2));
            rm = fmaxf(rm, __shfl_xor_sync(0xffffffffu, rm, 4));
            rm = fmaxf(rm, __shfl_xor_sync(0xffffffffu, rm, 8));
            float mnew = fmaxf(mi[i], rm);
            float alpha = __expf(mi[i] - mnew);
            float rs = 0.0f;
#pragma unroll
            for (int j = 0; j < 4; j++) {
                s[i][j] = __expf(s[i][j] - mnew);
                rs += s[i][j];
            }
            rs += __shfl_xor_sync(0xffffffffu, rs, 1);
            rs += __shfl_xor_sync(0xffffffffu, rs, 2);
            rs += __shfl_xor_sync(0xffffffffu, rs, 4);
            rs += __shfl_xor_sync(0xffffffffu, rs, 8);
            li[i] = li[i] * alpha + rs;
            mi[i] = mnew;
#pragma unroll
            for (int j = 0; j < 4; j++) o[i][j] *= alpha;
            // write P transposed: Pt[col][row]
#pragma unroll
            for (int j = 0; j < 4; j++)
                Pt[((tx << 2) + j) * FSTR + (ty << 2) + i] = s[i][j];
        }
        __syncthreads();

        // O += P @ V
#pragma unroll 8
        for (int kk = 0; kk < 64; kk++) {
            float pa[4], vb[4];
            *(float4*)pa = *(float4*)(Pt + kk * FSTR + (ty << 2));
            *(float4*)vb = *(float4*)(Vs + kk * FSTR + (tx << 2));
#pragma unroll
            for (int i = 0; i < 4; i++)
#pragma unroll
                for (int j = 0; j < 4; j++)
                    o[i][j] += pa[i] * vb[j];
        }
        __syncthreads();
    }

    // epilogue: O / l  -> global (layout [b, n, h*hd])
#pragma unroll
    for (int i = 0; i < 4; i++) {
        float inv = 1.0f / li[i];
        float4 v;
        v.x = o[i][0] * inv;
        v.y = o[i][1] * inv;
        v.z = o[i][2] * inv;
        v.w = o[i][3] * inv;
        *(float4*)(O + base + (size_t)(i0 + (ty << 2) + i) * DMODEL + (tx << 2)) = v;
    }
}

// ---------------------------------------------------------------------------
extern "C" void kernel_launch(void* const* d_in, const int* in_sizes, int n_in,
                              void* d_out, int out_size)
{
    (void)in_sizes; (void)n_in; (void)out_size;
    const float* x  = (const float*)d_in[0];
    const float* Wq = (const float*)d_in[1];
    const float* Wk = (const float*)d_in[2];
    const float* Wv = (const float*)d_in[3];
    const float* Wo = (const float*)d_in[4];
    const float* bo = (const float*)d_in[5];
    float* out = (float*)d_out;

    float *Qp, *Kp, *Vp, *AOp;
    cudaGetSymbolAddress((void**)&Qp,  g_Q);
    cudaGetSymbolAddress((void**)&Kp,  g_K);
    cudaGetSymbolAddress((void**)&Vp,  g_V);
    cudaGetSymbolAddress((void**)&AOp, g_AO);

    dim3 gemm_grid(NN / 128, MM / 128);
    sgemm_kernel<<<gemm_grid, 256>>>(x, Wq, Qp, nullptr);
    sgemm_kernel<<<gemm_grid, 256>>>(x, Wk, Kp, nullptr);
    sgemm_kernel<<<gemm_grid, 256>>>(x, Wv, Vp, nullptr);

    cudaFuncSetAttribute(flash_kernel,
                         cudaFuncAttributeMaxDynamicSharedMemorySize, FLASH_SMEM);
    dim3 flash_grid(SEQ / 64, BATCH * NHEAD);
    flash_kernel<<<flash_grid, 256, FLASH_SMEM>>>(Qp, Kp, Vp, AOp);

    sgemm_kernel<<<gemm_grid, 256>>>(AOp, Wo, out, bo);
}

// round 4
// speedup vs baseline: 1.4570x; 1.4570x over previous
#include <cuda_runtime.h>
#include <cuda_bf16.h>
#include <math.h>
#include <stdint.h>

// Fixed problem shape
#define BATCH 4
#define SEQ   2048
#define DMODEL 1024
#define NHEAD 16
#define HD    64
#define MM (BATCH*SEQ)     // 8192
#define KK DMODEL          // 1024
#define NN DMODEL          // 1024

// fp32 scratch
__device__ float g_Q[MM*NN];
__device__ float g_K[MM*NN];
__device__ float g_V[MM*NN];
__device__ float g_AO[MM*NN];
// bf16 split operands
__device__ __nv_bfloat16 g_Xhi[MM*KK];
__device__ __nv_bfloat16 g_Xlo[MM*KK];
__device__ __nv_bfloat16 g_Whi[4][NN*KK];   // transposed: [N][K]
__device__ __nv_bfloat16 g_Wlo[4][NN*KK];
__device__ __nv_bfloat16 g_AOhi[MM*KK];
__device__ __nv_bfloat16 g_AOlo[MM*KK];

// ---------------------------------------------------------------------------
__device__ __forceinline__ uint32_t smem_u32(const void* p) {
    uint32_t a;
    asm("{ .reg .u64 t; cvta.to.shared.u64 t, %1; cvt.u32.u64 %0, t; }"
        : "=r"(a) : "l"(p));
    return a;
}
__device__ __forceinline__ void cp_async16(uint32_t dst, const void* src) {
    asm volatile("cp.async.cg.shared.global [%0], [%1], 16;"
                 :: "r"(dst), "l"(src) : "memory");
}
__device__ __forceinline__ void mma_bf16(float* d, const uint32_t* a,
                                         uint32_t b0, uint32_t b1) {
    asm volatile(
        "mma.sync.aligned.m16n8k16.row.col.f32.bf16.bf16.f32 "
        "{%0,%1,%2,%3}, {%4,%5,%6,%7}, {%8,%9}, {%0,%1,%2,%3};"
        : "+f"(d[0]), "+f"(d[1]), "+f"(d[2]), "+f"(d[3])
        : "r"(a[0]), "r"(a[1]), "r"(a[2]), "r"(a[3]), "r"(b0), "r"(b1));
}
__device__ __forceinline__ void split_bf16(float x, __nv_bfloat16& h, __nv_bfloat16& l) {
    h = __float2bfloat16_rn(x);
    l = __float2bfloat16_rn(x - __bfloat162float(h));
}

// ---------------------------------------------------------------------------
// Convert fp32 -> bf16 hi/lo (grid-stride, float4)
// ---------------------------------------------------------------------------
__global__ __launch_bounds__(256) void convert_split(
    const float* __restrict__ src, __nv_bfloat16* __restrict__ hi,
    __nv_bfloat16* __restrict__ lo, int n4)
{
    int idx = blockIdx.x * blockDim.x + threadIdx.x;
    int stride = gridDim.x * blockDim.x;
    for (int i = idx; i < n4; i += stride) {
        float4 v = ((const float4*)src)[i];
        __nv_bfloat16 h[4], l[4];
        split_bf16(v.x, h[0], l[0]);
        split_bf16(v.y, h[1], l[1]);
        split_bf16(v.z, h[2], l[2]);
        split_bf16(v.w, h[3], l[3]);
        ((uint2*)hi)[i] = *(uint2*)h;
        ((uint2*)lo)[i] = *(uint2*)l;
    }
}

// ---------------------------------------------------------------------------
// Transpose + split 4 weights: W[K][N] fp32 -> WT hi/lo [N][K] bf16
// ---------------------------------------------------------------------------
__global__ __launch_bounds__(256) void transpose_split4(
    const float* __restrict__ s0, const float* __restrict__ s1,
    const float* __restrict__ s2, const float* __restrict__ s3)
{
    const float* s;
    __nv_bfloat16 *dh, *dl;
    switch (blockIdx.z) {
        case 0: s = s0; dh = g_Whi[0]; dl = g_Wlo[0]; break;
        case 1: s = s1; dh = g_Whi[1]; dl = g_Wlo[1]; break;
        case 2: s = s2; dh = g_Whi[2]; dl = g_Wlo[2]; break;
        default: s = s3; dh = g_Whi[3]; dl = g_Wlo[3]; break;
    }
    __shared__ float t[32][33];
    int x0 = blockIdx.x * 32, y0 = blockIdx.y * 32;   // x: N, y: K
    int tx = threadIdx.x, ty = threadIdx.y;           // 32 x 8
#pragma unroll
    for (int j = 0; j < 4; j++)
        t[ty + j * 8][tx] = s[(size_t)(y0 + ty + j * 8) * NN + x0 + tx];
    __syncthreads();
#pragma unroll
    for (int j = 0; j < 4; j++) {
        float v = t[tx][ty + j * 8];
        __nv_bfloat16 h, l;
        split_bf16(v, h, l);
        size_t o = (size_t)(x0 + ty + j * 8) * KK + y0 + tx;
        dh[o] = h;
        dl[o] = l;
    }
}

// ---------------------------------------------------------------------------
// bf16-split GEMM via mma.sync: C[M,N] = A[M,K] @ Bt[N,K]^T (+bias)
// Tile 128x128, BK=64, cp.async double-buffered, 256 threads (8 warps 4x2).
// smem rows padded to 144B for conflict-free fragment loads.
// ---------------------------------------------------------------------------
#define BKC 64
#define NCHUNKS (KK / BKC)            // 16
#define ROWB 144                      // padded row bytes (64 bf16 = 128B data)
#define ARR_BYTES (128 * ROWB)        // 18432
#define STAGE_BYTES (4 * ARR_BYTES)   // Ahi, Alo, Bhi, Blo
#define GEMM_SMEM (2 * STAGE_BYTES)   // 147456

__global__ __launch_bounds__(256, 1) void gemm_bf16(
    const __nv_bfloat16* __restrict__ Ahi, const __nv_bfloat16* __restrict__ Alo,
    const __nv_bfloat16* __restrict__ Bhi, const __nv_bfloat16* __restrict__ Blo,
    float* __restrict__ C, const float* __restrict__ bias)
{
    extern __shared__ __align__(16) char smb[];
    const uint32_t sbase = smem_u32(smb);
    const int tid = threadIdx.x;
    const int wid = tid >> 5;
    const int l = tid & 31;
    const int wm = wid & 3;       // m-block of 32
    const int wn = wid >> 2;      // n-block of 64
    const int m0 = blockIdx.y * 128;
    const int n0 = blockIdx.x * 128;

    float acc[2][8][4];
#pragma unroll
    for (int f = 0; f < 2; f++)
#pragma unroll
        for (int g = 0; g < 8; g++)
#pragma unroll
            for (int r = 0; r < 4; r++) acc[f][g][r] = 0.0f;

    // cp.async issue for chunk c into stage c&1
    auto issue = [&](int c) {
        const int kc0 = c * BKC;
        const uint32_t sb = sbase + (c & 1) * STAGE_BYTES;
#pragma unroll
        for (int i = 0; i < 16; i++) {
            int id = tid + i * 256;
            int arr = id >> 10;            // 0..3
            int rc = id & 1023;
            int row = rc >> 3;
            const __nv_bfloat16* gp;
            int grow;
            if (arr == 0)      { gp = Ahi; grow = m0 + row; }
            else if (arr == 1) { gp = Alo; grow = m0 + row; }
            else if (arr == 2) { gp = Bhi; grow = n0 + row; }
            else               { gp = Blo; grow = n0 + row; }
            const void* src = gp + (size_t)grow * KK + kc0 + (rc & 7) * 8;
            uint32_t dst = sb + arr * ARR_BYTES + row * ROWB + (rc & 7) * 16;
            cp_async16(dst, src);
        }
    };

    issue(0);
    asm volatile("cp.async.commit_group;" ::: "memory");

    const int lr = l >> 2;         // 0..7
    const int lc = (l & 3) * 2;    // k sub-col (bf16 elems)

    for (int c = 0; c < NCHUNKS; c++) {
        if (c + 1 < NCHUNKS) {
            issue(c + 1);
            asm volatile("cp.async.commit_group;" ::: "memory");
            asm volatile("cp.async.wait_group 1;" ::: "memory");
        } else {
            asm volatile("cp.async.wait_group 0;" ::: "memory");
        }
        __syncthreads();

        const char* sb = smb + (c & 1) * STAGE_BYTES;
#pragma unroll
        for (int ks = 0; ks < 4; ks++) {
            const int kc = ks * 16 + lc;     // bf16 col within chunk
            uint32_t ahi[2][4], alo[2][4];
#pragma unroll
            for (int f = 0; f < 2; f++) {
                int rowA = wm * 32 + f * 16 + lr;
                const char* pa = sb + rowA * ROWB + kc * 2;
                ahi[f][0] = *(const uint32_t*)(pa);
                ahi[f][1] = *(const uint32_t*)(pa + 8 * ROWB);
                ahi[f][2] = *(const uint32_t*)(pa + 16);
                ahi[f][3] = *(const uint32_t*)(pa + 8 * ROWB + 16);
                const char* pl = pa + ARR_BYTES;
                alo[f][0] = *(const uint32_t*)(pl);
                alo[f][1] = *(const uint32_t*)(pl + 8 * ROWB);
                alo[f][2] = *(const uint32_t*)(pl + 16);
                alo[f][3] = *(const uint32_t*)(pl + 8 * ROWB + 16);
            }
#pragma unroll
            for (int g = 0; g < 8; g++) {
                int rowBn = wn * 64 + g * 8 + lr;
                const char* pb = sb + 2 * ARR_BYTES + rowBn * ROWB + kc * 2;
                uint32_t bh0 = *(const uint32_t*)(pb);
                uint32_t bh1 = *(const uint32_t*)(pb + 16);
                uint32_t bl0 = *(const uint32_t*)(pb + ARR_BYTES);
                uint32_t bl1 = *(const uint32_t*)(pb + ARR_BYTES + 16);
#pragma unroll
                for (int f = 0; f < 2; f++) {
                    mma_bf16(acc[f][g], ahi[f], bh0, bh1);
                    mma_bf16(acc[f][g], ahi[f], bl0, bl1);
                    mma_bf16(acc[f][g], alo[f], bh0, bh1);
                }
            }
        }
        __syncthreads();
    }

    // Epilogue
#pragma unroll
    for (int f = 0; f < 2; f++) {
        int r0 = m0 + wm * 32 + f * 16 + lr;
#pragma unroll
        for (int g = 0; g < 8; g++) {
            int cc = n0 + wn * 64 + g * 8 + lc;
            float bx = 0.f, by = 0.f;
            if (bias) { bx = bias[cc]; by = bias[cc + 1]; }
            float2 v0 = make_float2(acc[f][g][0] + bx, acc[f][g][1] + by);
            float2 v1 = make_float2(acc[f][g][2] + bx, acc[f][g][3] + by);
            *(float2*)(C + (size_t)r0 * NN + cc) = v0;
            *(float2*)(C + (size_t)(r0 + 8) * NN + cc) = v1;
        }
    }
}

// ---------------------------------------------------------------------------
// Flash attention (causal), fp32. BM=BN=64, d=64.  (unchanged — R1 verified)
// ---------------------------------------------------------------------------
#define FSTR 68
#define FLASH_SMEM (4 * 64 * FSTR * 4)

__global__ __launch_bounds__(256) void flash_kernel(
    const float* __restrict__ Q, const float* __restrict__ K,
    const float* __restrict__ V, float* __restrict__ O)
{
    extern __shared__ float smf[];
    float* Qt = smf;
    float* Kt = smf + 1 * 64 * FSTR;
    float* Vs = smf + 2 * 64 * FSTR;
    float* Pt = smf + 3 * 64 * FSTR;

    const int tid = threadIdx.x;
    const int tx = tid & 15;
    const int ty = tid >> 4;
    const int ib = blockIdx.x;
    const int bh = blockIdx.y;
    const int b = bh >> 4;
    const int head = bh & 15;
    const size_t base = (size_t)b * SEQ * DMODEL + (size_t)head * HD;
    const int i0 = ib * 64;

    {
        const int lrow = tid >> 4;
        const int lcol = (tid & 15) << 2;
#pragma unroll
        for (int p = 0; p < 4; p++) {
            int row = lrow + p * 16;
            float4 v = *(const float4*)(Q + base + (size_t)(i0 + row) * DMODEL + lcol);
            Qt[(lcol + 0) * FSTR + row] = v.x * 0.125f;
            Qt[(lcol + 1) * FSTR + row] = v.y * 0.125f;
            Qt[(lcol + 2) * FSTR + row] = v.z * 0.125f;
            Qt[(lcol + 3) * FSTR + row] = v.w * 0.125f;
        }
    }

    float o[4][4];
#pragma unroll
    for (int i = 0; i < 4; i++)
#pragma unroll
        for (int j = 0; j < 4; j++) o[i][j] = 0.0f;
    float mi[4] = {-1e30f, -1e30f, -1e30f, -1e30f};
    float li[4] = {0.f, 0.f, 0.f, 0.f};

    for (int jb = 0; jb <= ib; jb++) {
        const int j0 = jb * 64;
        {
            const int lrow = tid >> 4;
            const int lcol = (tid & 15) << 2;
#pragma unroll
            for (int p = 0; p < 4; p++) {
                int row = lrow + p * 16;
                float4 kv = *(const float4*)(K + base + (size_t)(j0 + row) * DMODEL + lcol);
                Kt[(lcol + 0) * FSTR + row] = kv.x;
                Kt[(lcol + 1) * FSTR + row] = kv.y;
                Kt[(lcol + 2) * FSTR + row] = kv.z;
                Kt[(lcol + 3) * FSTR + row] = kv.w;
                float4 vv = *(const float4*)(V + base + (size_t)(j0 + row) * DMODEL + lcol);
                *(float4*)(Vs + (size_t)row * FSTR + lcol) = vv;
            }
        }
        __syncthreads();

        float s[4][4];
#pragma unroll
        for (int i = 0; i < 4; i++)
#pragma unroll
            for (int j = 0; j < 4; j++) s[i][j] = 0.0f;

#pragma unroll 8
        for (int d = 0; d < 64; d++) {
            float qa[4], kb[4];
            *(float4*)qa = *(float4*)(Qt + d * FSTR + (ty << 2));
            *(float4*)kb = *(float4*)(Kt + d * FSTR + (tx << 2));
#pragma unroll
            for (int i = 0; i < 4; i++)
#pragma unroll
                for (int j = 0; j < 4; j++)
                    s[i][j] += qa[i] * kb[j];
        }

        if (jb == ib) {
#pragma unroll
            for (int i = 0; i < 4; i++)
#pragma unroll
                for (int j = 0; j < 4; j++)
                    if (((tx << 2) + j) > ((ty << 2) + i)) s[i][j] = -1e30f;
        }

#pragma unroll
        for (int i = 0; i < 4; i++) {
            float rm = s[i][0];
            rm = fmaxf(rm, s[i][1]);
            rm = fmaxf(rm, s[i][2]);
            rm = fmaxf(rm, s[i][3]);
            rm = fmaxf(rm, __shfl_xor_sync(0xffffffffu, rm, 1));
            rm = fmaxf(rm, __shfl_xor_sync(0xffffffffu, rm, 2));
            rm = fmaxf(rm, __shfl_xor_sync(0xffffffffu, rm, 4));
            rm = fmaxf(rm, __shfl_xor_sync(0xffffffffu, rm, 8));
            float mnew = fmaxf(mi[i], rm);
            float alpha = __expf(mi[i] - mnew);
            float rs = 0.0f;
#pragma unroll
            for (int j = 0; j < 4; j++) {
                s[i][j] = __expf(s[i][j] - mnew);
                rs += s[i][j];
            }
            rs += __shfl_xor_sync(0xffffffffu, rs, 1);
            rs += __shfl_xor_sync(0xffffffffu, rs, 2);
            rs += __shfl_xor_sync(0xffffffffu, rs, 4);
            rs += __shfl_xor_sync(0xffffffffu, rs, 8);
            li[i] = li[i] * alpha + rs;
            mi[i] = mnew;
#pragma unroll
            for (int j = 0; j < 4; j++) o[i][j] *= alpha;
#pragma unroll
            for (int j = 0; j < 4; j++)
                Pt[((tx << 2) + j) * FSTR + (ty << 2) + i] = s[i][j];
        }
        __syncthreads();

#pragma unroll 8
        for (int kk = 0; kk < 64; kk++) {
            float pa[4], vb[4];
            *(float4*)pa = *(float4*)(Pt + kk * FSTR + (ty << 2));
            *(float4*)vb = *(float4*)(Vs + kk * FSTR + (tx << 2));
#pragma unroll
            for (int i = 0; i < 4; i++)
#pragma unroll
                for (int j = 0; j < 4; j++)
                    o[i][j] += pa[i] * vb[j];
        }
        __syncthreads();
    }

#pragma unroll
    for (int i = 0; i < 4; i++) {
        float inv = 1.0f / li[i];
        float4 v;
        v.x = o[i][0] * inv;
        v.y = o[i][1] * inv;
        v.z = o[i][2] * inv;
        v.w = o[i][3] * inv;
        *(float4*)(O + base + (size_t)(i0 + (ty << 2) + i) * DMODEL + (tx << 2)) = v;
    }
}

// ---------------------------------------------------------------------------
extern "C" void kernel_launch(void* const* d_in, const int* in_sizes, int n_in,
                              void* d_out, int out_size)
{
    (void)in_sizes; (void)n_in; (void)out_size;
    const float* x  = (const float*)d_in[0];
    const float* Wq = (const float*)d_in[1];
    const float* Wk = (const float*)d_in[2];
    const float* Wv = (const float*)d_in[3];
    const float* Wo = (const float*)d_in[4];
    const float* bo = (const float*)d_in[5];
    float* out = (float*)d_out;

    float *Qp, *Kp, *Vp, *AOp;
    __nv_bfloat16 *Xhi, *Xlo, *AOhi, *AOlo, *Whi, *Wlo;
    cudaGetSymbolAddress((void**)&Qp,   g_Q);
    cudaGetSymbolAddress((void**)&Kp,   g_K);
    cudaGetSymbolAddress((void**)&Vp,   g_V);
    cudaGetSymbolAddress((void**)&AOp,  g_AO);
    cudaGetSymbolAddress((void**)&Xhi,  g_Xhi);
    cudaGetSymbolAddress((void**)&Xlo,  g_Xlo);
    cudaGetSymbolAddress((void**)&AOhi, g_AOhi);
    cudaGetSymbolAddress((void**)&AOlo, g_AOlo);
    cudaGetSymbolAddress((void**)&Whi,  g_Whi);
    cudaGetSymbolAddress((void**)&Wlo,  g_Wlo);

    // 1. convert x -> bf16 hi/lo
    convert_split<<<512, 256>>>(x, Xhi, Xlo, MM * KK / 4);
    // 2. transpose + split weights
    transpose_split4<<<dim3(32, 32, 4), dim3(32, 8)>>>(Wq, Wk, Wv, Wo);

    cudaFuncSetAttribute(gemm_bf16, cudaFuncAttributeMaxDynamicSharedMemorySize, GEMM_SMEM);
    dim3 gg(NN / 128, MM / 128);
    gemm_bf16<<<gg, 256, GEMM_SMEM>>>(Xhi, Xlo, Whi + 0 * (size_t)NN * KK,
                                      Wlo + 0 * (size_t)NN * KK, Qp, nullptr);
    gemm_bf16<<<gg, 256, GEMM_SMEM>>>(Xhi, Xlo, Whi + 1 * (size_t)NN * KK,
                                      Wlo + 1 * (size_t)NN * KK, Kp, nullptr);
    gemm_bf16<<<gg, 256, GEMM_SMEM>>>(Xhi, Xlo, Whi + 2 * (size_t)NN * KK,
                                      Wlo + 2 * (size_t)NN * KK, Vp, nullptr);

    cudaFuncSetAttribute(flash_kernel, cudaFuncAttributeMaxDynamicSharedMemorySize, FLASH_SMEM);
    dim3 fg(SEQ / 64, BATCH * NHEAD);
    flash_kernel<<<fg, 256, FLASH_SMEM>>>(Qp, Kp, Vp, AOp);

    convert_split<<<512, 256>>>(AOp, AOhi, AOlo, MM * KK / 4);
    gemm_bf16<<<gg, 256, GEMM_SMEM>>>(AOhi, AOlo, Whi + 3 * (size_t)NN * KK,
                                      Wlo + 3 * (size_t)NN * KK, out, bo);
}

// round 5
// speedup vs baseline: 2.5705x; 1.7643x over previous
#include <cuda_runtime.h>
#include <cuda_bf16.h>
#include <math.h>
#include <stdint.h>

// Fixed problem shape
#define BATCH 4
#define SEQ   2048
#define DMODEL 1024
#define NHEAD 16
#define HD    64
#define MM (BATCH*SEQ)     // 8192
#define KK DMODEL          // 1024
#define NN DMODEL          // 1024

// bf16 split operands (device globals; no allocation allowed)
__device__ __nv_bfloat16 g_Xhi[MM*KK];
__device__ __nv_bfloat16 g_Xlo[MM*KK];
__device__ __nv_bfloat16 g_Whi[4][NN*KK];   // transposed weights [N][K]
__device__ __nv_bfloat16 g_Wlo[4][NN*KK];
__device__ __nv_bfloat16 g_Qhi[MM*NN];      // [b*SEQ+n][h*64+d], pre-scaled 0.125
__device__ __nv_bfloat16 g_Qlo[MM*NN];
__device__ __nv_bfloat16 g_Khi[MM*NN];
__device__ __nv_bfloat16 g_Klo[MM*NN];
__device__ __nv_bfloat16 g_Vthi[MM*NN];     // [(b*16+h)*64+d][key]  (transposed)
__device__ __nv_bfloat16 g_Vtlo[MM*NN];
__device__ __nv_bfloat16 g_AOhi[MM*NN];
__device__ __nv_bfloat16 g_AOlo[MM*NN];

// ---------------------------------------------------------------------------
__device__ __forceinline__ uint32_t smem_u32(const void* p) {
    uint32_t a;
    asm("{ .reg .u64 t; cvta.to.shared.u64 t, %1; cvt.u32.u64 %0, t; }"
        : "=r"(a) : "l"(p));
    return a;
}
__device__ __forceinline__ void cp_async16(uint32_t dst, const void* src) {
    asm volatile("cp.async.cg.shared.global [%0], [%1], 16;"
                 :: "r"(dst), "l"(src) : "memory");
}
__device__ __forceinline__ void mma_bf16(float* d, const uint32_t* a,
                                         uint32_t b0, uint32_t b1) {
    asm volatile(
        "mma.sync.aligned.m16n8k16.row.col.f32.bf16.bf16.f32 "
        "{%0,%1,%2,%3}, {%4,%5,%6,%7}, {%8,%9}, {%0,%1,%2,%3};"
        : "+f"(d[0]), "+f"(d[1]), "+f"(d[2]), "+f"(d[3])
        : "r"(a[0]), "r"(a[1]), "r"(a[2]), "r"(a[3]), "r"(b0), "r"(b1));
}
__device__ __forceinline__ void split_bf16(float x, __nv_bfloat16& h, __nv_bfloat16& l) {
    h = __float2bfloat16_rn(x);
    l = __float2bfloat16_rn(x - __bfloat162float(h));
}
// pack two floats -> (hiPair, loPair) u32 of bf16x2
__device__ __forceinline__ void split_pack2(float f0, float f1,
                                            uint32_t& hp, uint32_t& lp) {
    __nv_bfloat16 h0, l0, h1, l1;
    split_bf16(f0, h0, l0);
    split_bf16(f1, h1, l1);
    hp = ((uint32_t)*(uint16_t*)&h1 << 16) | *(uint16_t*)&h0;
    lp = ((uint32_t)*(uint16_t*)&l1 << 16) | *(uint16_t*)&l0;
}

// ---------------------------------------------------------------------------
// Convert fp32 -> bf16 hi/lo (grid-stride, float4)
// ---------------------------------------------------------------------------
__global__ __launch_bounds__(256) void convert_split(
    const float* __restrict__ src, __nv_bfloat16* __restrict__ hi,
    __nv_bfloat16* __restrict__ lo, int n4)
{
    int idx = blockIdx.x * blockDim.x + threadIdx.x;
    int stride = gridDim.x * blockDim.x;
    for (int i = idx; i < n4; i += stride) {
        float4 v = ((const float4*)src)[i];
        __nv_bfloat16 h[4], l[4];
        split_bf16(v.x, h[0], l[0]);
        split_bf16(v.y, h[1], l[1]);
        split_bf16(v.z, h[2], l[2]);
        split_bf16(v.w, h[3], l[3]);
        ((uint2*)hi)[i] = *(uint2*)h;
        ((uint2*)lo)[i] = *(uint2*)l;
    }
}

// ---------------------------------------------------------------------------
// Transpose + split 4 weights: W[K][N] fp32 -> WT hi/lo [N][K] bf16
// ---------------------------------------------------------------------------
__global__ __launch_bounds__(256) void transpose_split4(
    const float* __restrict__ s0, const float* __restrict__ s1,
    const float* __restrict__ s2, const float* __restrict__ s3)
{
    const float* s;
    __nv_bfloat16 *dh, *dl;
    switch (blockIdx.z) {
        case 0: s = s0; dh = g_Whi[0]; dl = g_Wlo[0]; break;
        case 1: s = s1; dh = g_Whi[1]; dl = g_Wlo[1]; break;
        case 2: s = s2; dh = g_Whi[2]; dl = g_Wlo[2]; break;
        default: s = s3; dh = g_Whi[3]; dl = g_Wlo[3]; break;
    }
    __shared__ float t[32][33];
    int x0 = blockIdx.x * 32, y0 = blockIdx.y * 32;
    int tx = threadIdx.x, ty = threadIdx.y;
#pragma unroll
    for (int j = 0; j < 4; j++)
        t[ty + j * 8][tx] = s[(size_t)(y0 + ty + j * 8) * NN + x0 + tx];
    __syncthreads();
#pragma unroll
    for (int j = 0; j < 4; j++) {
        float v = t[tx][ty + j * 8];
        __nv_bfloat16 h, l;
        split_bf16(v, h, l);
        size_t o = (size_t)(x0 + ty + j * 8) * KK + y0 + tx;
        dh[o] = h;
        dl[o] = l;
    }
}

// ---------------------------------------------------------------------------
// bf16-split GEMM via mma.sync (verified R4). MODE:
//   0 = fp32 out C + bias (final projection)
//   1 = bf16 hi/lo out, natural [M][NN] layout, scaled (Q/K projections)
//   2 = bf16 hi/lo out, transposed per-head [bh*64+d][key] layout (V)
// ---------------------------------------------------------------------------
#define BKC 64
#define NCHUNKS (KK / BKC)            // 16
#define ROWB 144
#define ARR_BYTES (128 * ROWB)
#define STAGE_BYTES (4 * ARR_BYTES)
#define GEMM_SMEM (2 * STAGE_BYTES)   // 147456

template <int MODE>
__global__ __launch_bounds__(256, 1) void gemm_bf16(
    const __nv_bfloat16* __restrict__ Ahi, const __nv_bfloat16* __restrict__ Alo,
    const __nv_bfloat16* __restrict__ Bhi, const __nv_bfloat16* __restrict__ Blo,
    float* __restrict__ C, const float* __restrict__ bias,
    __nv_bfloat16* __restrict__ Ohi, __nv_bfloat16* __restrict__ Olo,
    float scale)
{
    extern __shared__ __align__(16) char smb[];
    const uint32_t sbase = smem_u32(smb);
    const int tid = threadIdx.x;
    const int wid = tid >> 5;
    const int l = tid & 31;
    const int wm = wid & 3;
    const int wn = wid >> 2;
    const int m0 = blockIdx.y * 128;
    const int n0 = blockIdx.x * 128;

    float acc[2][8][4];
#pragma unroll
    for (int f = 0; f < 2; f++)
#pragma unroll
        for (int g = 0; g < 8; g++)
#pragma unroll
            for (int r = 0; r < 4; r++) acc[f][g][r] = 0.0f;

    auto issue = [&](int c) {
        const int kc0 = c * BKC;
        const uint32_t sb = sbase + (c & 1) * STAGE_BYTES;
#pragma unroll
        for (int i = 0; i < 16; i++) {
            int id = tid + i * 256;
            int arr = id >> 10;
            int rc = id & 1023;
            int row = rc >> 3;
            const __nv_bfloat16* gp;
            int grow;
            if (arr == 0)      { gp = Ahi; grow = m0 + row; }
            else if (arr == 1) { gp = Alo; grow = m0 + row; }
            else if (arr == 2) { gp = Bhi; grow = n0 + row; }
            else               { gp = Blo; grow = n0 + row; }
            const void* src = gp + (size_t)grow * KK + kc0 + (rc & 7) * 8;
            uint32_t dst = sb + arr * ARR_BYTES + row * ROWB + (rc & 7) * 16;
            cp_async16(dst, src);
        }
    };

    issue(0);
    asm volatile("cp.async.commit_group;" ::: "memory");

    const int lr = l >> 2;
    const int lc = (l & 3) * 2;

    for (int c = 0; c < NCHUNKS; c++) {
        if (c + 1 < NCHUNKS) {
            issue(c + 1);
            asm volatile("cp.async.commit_group;" ::: "memory");
            asm volatile("cp.async.wait_group 1;" ::: "memory");
        } else {
            asm volatile("cp.async.wait_group 0;" ::: "memory");
        }
        __syncthreads();

        const char* sb = smb + (c & 1) * STAGE_BYTES;
#pragma unroll
        for (int ks = 0; ks < 4; ks++) {
            const int kc = ks * 16 + lc;
            uint32_t ahi[2][4], alo[2][4];
#pragma unroll
            for (int f = 0; f < 2; f++) {
                int rowA = wm * 32 + f * 16 + lr;
                const char* pa = sb + rowA * ROWB + kc * 2;
                ahi[f][0] = *(const uint32_t*)(pa);
                ahi[f][1] = *(const uint32_t*)(pa + 8 * ROWB);
                ahi[f][2] = *(const uint32_t*)(pa + 16);
                ahi[f][3] = *(const uint32_t*)(pa + 8 * ROWB + 16);
                const char* pl = pa + ARR_BYTES;
                alo[f][0] = *(const uint32_t*)(pl);
                alo[f][1] = *(const uint32_t*)(pl + 8 * ROWB);
                alo[f][2] = *(const uint32_t*)(pl + 16);
                alo[f][3] = *(const uint32_t*)(pl + 8 * ROWB + 16);
            }
#pragma unroll
            for (int g = 0; g < 8; g++) {
                int rowBn = wn * 64 + g * 8 + lr;
                const char* pb = sb + 2 * ARR_BYTES + rowBn * ROWB + kc * 2;
                uint32_t bh0 = *(const uint32_t*)(pb);
                uint32_t bh1 = *(const uint32_t*)(pb + 16);
                uint32_t bl0 = *(const uint32_t*)(pb + ARR_BYTES);
                uint32_t bl1 = *(const uint32_t*)(pb + ARR_BYTES + 16);
#pragma unroll
                for (int f = 0; f < 2; f++) {
                    mma_bf16(acc[f][g], ahi[f], bh0, bh1);
                    mma_bf16(acc[f][g], ahi[f], bl0, bl1);
                    mma_bf16(acc[f][g], alo[f], bh0, bh1);
                }
            }
        }
        __syncthreads();
    }

    // Epilogue
#pragma unroll
    for (int f = 0; f < 2; f++) {
        int r0 = m0 + wm * 32 + f * 16 + lr;
#pragma unroll
        for (int g = 0; g < 8; g++) {
            int cc = n0 + wn * 64 + g * 8 + lc;
            if (MODE == 0) {
                float bx = bias[cc], by = bias[cc + 1];
                float2 v0 = make_float2(acc[f][g][0] + bx, acc[f][g][1] + by);
                float2 v1 = make_float2(acc[f][g][2] + bx, acc[f][g][3] + by);
                *(float2*)(C + (size_t)r0 * NN + cc) = v0;
                *(float2*)(C + (size_t)(r0 + 8) * NN + cc) = v1;
            } else if (MODE == 1) {
                uint32_t hp, lp;
                split_pack2(acc[f][g][0] * scale, acc[f][g][1] * scale, hp, lp);
                *(uint32_t*)(Ohi + (size_t)r0 * NN + cc) = hp;
                *(uint32_t*)(Olo + (size_t)r0 * NN + cc) = lp;
                split_pack2(acc[f][g][2] * scale, acc[f][g][3] * scale, hp, lp);
                *(uint32_t*)(Ohi + (size_t)(r0 + 8) * NN + cc) = hp;
                *(uint32_t*)(Olo + (size_t)(r0 + 8) * NN + cc) = lp;
            } else {
                // transposed per-head: dst[(b*16+h)*64 + d][key]
#pragma unroll
                for (int rr = 0; rr < 2; rr++) {
                    int row = r0 + rr * 8;
                    int b = row >> 11, n = row & 2047;
#pragma unroll
                    for (int cj = 0; cj < 2; cj++) {
                        int col = cc + cj;           // = h*64 + d
                        float v = acc[f][g][rr * 2 + cj];
                        __nv_bfloat16 h, lo2;
                        split_bf16(v, h, lo2);
                        size_t o = ((size_t)(b * 16) * 64 + col) * SEQ + n;
                        Ohi[o] = h;
                        Olo[o] = lo2;
                    }
                }
            }
        }
    }
}

// ---------------------------------------------------------------------------
// Tensor-core flash attention (causal), bf16 3-term split.
// BM=BN=64, d=64. 128 threads (4 warps; warp w owns rows w*16..w*16+15).
// K/Vt cp.async double-buffered. P hi/lo staged in smem (warp-local rows).
// ---------------------------------------------------------------------------
#define FQ_HI 0
#define FQ_LO 9216
#define FK_BASE 18432
#define FV_BASE 55296
#define FP_HI 92160
#define FP_LO 101376
#define FLASH_SMEM 110592

__global__ __launch_bounds__(128, 2) void flash_tc(
    const __nv_bfloat16* __restrict__ Qhi, const __nv_bfloat16* __restrict__ Qlo,
    const __nv_bfloat16* __restrict__ Khi, const __nv_bfloat16* __restrict__ Klo,
    const __nv_bfloat16* __restrict__ Vthi, const __nv_bfloat16* __restrict__ Vtlo,
    __nv_bfloat16* __restrict__ AOhi, __nv_bfloat16* __restrict__ AOlo)
{
    extern __shared__ __align__(16) char smf[];
    const uint32_t sb = smem_u32(smf);
    const int tid = threadIdx.x;
    const int w = tid >> 5;
    const int l = tid & 31;
    const int lr = l >> 2;
    const int lq = l & 3;
    const int ib = gridDim.x - 1 - blockIdx.x;   // long CTAs launch first
    const int bh = blockIdx.y;
    const int b = bh >> 4;
    const int h = bh & 15;
    const int i0 = ib * 64;
    const size_t qrow0 = (size_t)b * SEQ + i0;

    // ---- load Q (hi+lo) ----
#pragma unroll
    for (int i = 0; i < 8; i++) {
        int id = tid + i * 128;
        int arr = id >> 9;
        int rc = id & 511;
        int row = rc >> 3, ch = rc & 7;
        const __nv_bfloat16* gp = arr ? Qlo : Qhi;
        cp_async16(sb + arr * 9216 + row * 144 + ch * 16,
                   gp + (qrow0 + row) * DMODEL + h * 64 + ch * 8);
    }

    auto issueKV = [&](int jb) {
        const int s = jb & 1;
        const int j0 = jb * 64;
#pragma unroll
        for (int i = 0; i < 16; i++) {
            int id = tid + i * 128;
            int half = id >> 10;           // 0=K, 1=Vt
            int rc = id & 1023;
            int arr = rc >> 9;             // 0=hi, 1=lo
            int r2 = rc & 511;
            int row = r2 >> 3, ch = r2 & 7;
            const __nv_bfloat16* gp;
            const void* src;
            uint32_t dst;
            if (half == 0) {
                gp = arr ? Klo : Khi;
                src = gp + ((size_t)b * SEQ + j0 + row) * DMODEL + h * 64 + ch * 8;
                dst = sb + FK_BASE + s * 18432 + arr * 9216 + row * 144 + ch * 16;
            } else {
                gp = arr ? Vtlo : Vthi;
                src = gp + ((size_t)bh * 64 + row) * SEQ + j0 + ch * 8;
                dst = sb + FV_BASE + s * 18432 + arr * 9216 + row * 144 + ch * 16;
            }
            cp_async16(dst, src);
        }
    };

    issueKV(0);
    asm volatile("cp.async.commit_group;" ::: "memory");

    float mrow[2] = {-1e30f, -1e30f};
    float lsum[2] = {0.0f, 0.0f};
    float oacc[8][4];
#pragma unroll
    for (int g = 0; g < 8; g++)
#pragma unroll
        for (int r = 0; r < 4; r++) oacc[g][r] = 0.0f;

    for (int jb = 0; jb <= ib; jb++) {
        const int s = jb & 1;
        if (jb < ib) {
            issueKV(jb + 1);
            asm volatile("cp.async.commit_group;" ::: "memory");
            asm volatile("cp.async.wait_group 1;" ::: "memory");
        } else {
            asm volatile("cp.async.wait_group 0;" ::: "memory");
        }
        __syncthreads();

        // ---- S = Q @ K^T (3-term split) ----
        float sacc[8][4];
#pragma unroll
        for (int g = 0; g < 8; g++)
#pragma unroll
            for (int r = 0; r < 4; r++) sacc[g][r] = 0.0f;

        const char* qh = smf;
        const char* kb = smf + FK_BASE + s * 18432;
#pragma unroll
        for (int ks = 0; ks < 4; ks++) {
            const int kc = ks * 32 + lq * 4;   // byte offset along k
            uint32_t ahi[4], alo[4];
            {
                const char* pa = qh + (w * 16 + lr) * 144 + kc;
                ahi[0] = *(const uint32_t*)(pa);
                ahi[1] = *(const uint32_t*)(pa + 8 * 144);
                ahi[2] = *(const uint32_t*)(pa + 16);
                ahi[3] = *(const uint32_t*)(pa + 8 * 144 + 16);
                const char* pl = pa + 9216;
                alo[0] = *(const uint32_t*)(pl);
                alo[1] = *(const uint32_t*)(pl + 8 * 144);
                alo[2] = *(const uint32_t*)(pl + 16);
                alo[3] = *(const uint32_t*)(pl + 8 * 144 + 16);
            }
#pragma unroll
            for (int g = 0; g < 8; g++) {
                const char* pb = kb + (g * 8 + lr) * 144 + kc;
                uint32_t bh0 = *(const uint32_t*)(pb);
                uint32_t bh1 = *(const uint32_t*)(pb + 16);
                uint32_t bl0 = *(const uint32_t*)(pb + 9216);
                uint32_t bl1 = *(const uint32_t*)(pb + 9216 + 16);
                mma_bf16(sacc[g], ahi, bh0, bh1);
                mma_bf16(sacc[g], ahi, bl0, bl1);
                mma_bf16(sacc[g], alo, bh0, bh1);
            }
        }

        // ---- causal mask on diagonal block ----
        if (jb == ib) {
#pragma unroll
            for (int g = 0; g < 8; g++)
#pragma unroll
                for (int r = 0; r < 4; r++) {
                    int rowL = w * 16 + lr + (r >> 1) * 8;
                    int colL = g * 8 + lq * 2 + (r & 1);
                    if (colL > rowL) sacc[g][r] = -1e30f;
                }
        }

        // ---- online softmax + P split to smem ----
#pragma unroll
        for (int ri = 0; ri < 2; ri++) {
            const int c0 = ri * 2;
            float rmax = -1e30f;
#pragma unroll
            for (int g = 0; g < 8; g++)
                rmax = fmaxf(rmax, fmaxf(sacc[g][c0], sacc[g][c0 + 1]));
            rmax = fmaxf(rmax, __shfl_xor_sync(0xffffffffu, rmax, 1));
            rmax = fmaxf(rmax, __shfl_xor_sync(0xffffffffu, rmax, 2));
            float mnew = fmaxf(mrow[ri], rmax);
            float alpha = __expf(mrow[ri] - mnew);
            float rsum = 0.0f;
            const int prow = w * 16 + lr + ri * 8;
#pragma unroll
            for (int g = 0; g < 8; g++) {
                float p0 = __expf(sacc[g][c0] - mnew);
                float p1 = __expf(sacc[g][c0 + 1] - mnew);
                rsum += p0 + p1;
                uint32_t hp, lp;
                split_pack2(p0, p1, hp, lp);
                int boff = prow * 144 + (g * 8 + lq * 2) * 2;
                *(uint32_t*)(smf + FP_HI + boff) = hp;
                *(uint32_t*)(smf + FP_LO + boff) = lp;
            }
            rsum += __shfl_xor_sync(0xffffffffu, rsum, 1);
            rsum += __shfl_xor_sync(0xffffffffu, rsum, 2);
            lsum[ri] = lsum[ri] * alpha + rsum;
            mrow[ri] = mnew;
#pragma unroll
            for (int g = 0; g < 8; g++) {
                oacc[g][c0] *= alpha;
                oacc[g][c0 + 1] *= alpha;
            }
        }
        __syncwarp();

        // ---- O += P @ V  (B = Vt[d][key], 3-term split) ----
        const char* vb = smf + FV_BASE + s * 18432;
#pragma unroll
        for (int ks = 0; ks < 4; ks++) {
            const int kc = ks * 32 + lq * 4;
            uint32_t phi[4], plo[4];
            {
                const char* pa = smf + FP_HI + (w * 16 + lr) * 144 + kc;
                phi[0] = *(const uint32_t*)(pa);
                phi[1] = *(const uint32_t*)(pa + 8 * 144);
                phi[2] = *(const uint32_t*)(pa + 16);
                phi[3] = *(const uint32_t*)(pa + 8 * 144 + 16);
                const char* pl = smf + FP_LO + (w * 16 + lr) * 144 + kc;
                plo[0] = *(const uint32_t*)(pl);
                plo[1] = *(const uint32_t*)(pl + 8 * 144);
                plo[2] = *(const uint32_t*)(pl + 16);
                plo[3] = *(const uint32_t*)(pl + 8 * 144 + 16);
            }
#pragma unroll
            for (int g = 0; g < 8; g++) {
                const char* pb = vb + (g * 8 + lr) * 144 + kc;
                uint32_t bh0 = *(const uint32_t*)(pb);
                uint32_t bh1 = *(const uint32_t*)(pb + 16);
                uint32_t bl0 = *(const uint32_t*)(pb + 9216);
                uint32_t bl1 = *(const uint32_t*)(pb + 9216 + 16);
                mma_bf16(oacc[g], phi, bh0, bh1);
                mma_bf16(oacc[g], phi, bl0, bl1);
                mma_bf16(oacc[g], plo, bh0, bh1);
            }
        }
        __syncthreads();   // stage reuse barrier
    }

    // ---- epilogue: AO = O / l -> bf16 hi/lo ----
#pragma unroll
    for (int ri = 0; ri < 2; ri++) {
        float inv = 1.0f / lsum[ri];
        size_t grow = qrow0 + w * 16 + lr + ri * 8;
#pragma unroll
        for (int g = 0; g < 8; g++) {
            int col = h * 64 + g * 8 + lq * 2;
            uint32_t hp, lp;
            split_pack2(oacc[g][ri * 2] * inv, oacc[g][ri * 2 + 1] * inv, hp, lp);
            *(uint32_t*)(AOhi + grow * DMODEL + col) = hp;
            *(uint32_t*)(AOlo + grow * DMODEL + col) = lp;
        }
    }
}

// ---------------------------------------------------------------------------
extern "C" void kernel_launch(void* const* d_in, const int* in_sizes, int n_in,
                              void* d_out, int out_size)
{
    (void)in_sizes; (void)n_in; (void)out_size;
    const float* x  = (const float*)d_in[0];
    const float* Wq = (const float*)d_in[1];
    const float* Wk = (const float*)d_in[2];
    const float* Wv = (const float*)d_in[3];
    const float* Wo = (const float*)d_in[4];
    const float* bo = (const float*)d_in[5];
    float* out = (float*)d_out;

    __nv_bfloat16 *Xhi, *Xlo, *Whi, *Wlo, *Qhi, *Qlo, *Khi, *Klo,
                  *Vthi, *Vtlo, *AOhi, *AOlo;
    cudaGetSymbolAddress((void**)&Xhi,  g_Xhi);
    cudaGetSymbolAddress((void**)&Xlo,  g_Xlo);
    cudaGetSymbolAddress((void**)&Whi,  g_Whi);
    cudaGetSymbolAddress((void**)&Wlo,  g_Wlo);
    cudaGetSymbolAddress((void**)&Qhi,  g_Qhi);
    cudaGetSymbolAddress((void**)&Qlo,  g_Qlo);
    cudaGetSymbolAddress((void**)&Khi,  g_Khi);
    cudaGetSymbolAddress((void**)&Klo,  g_Klo);
    cudaGetSymbolAddress((void**)&Vthi, g_Vthi);
    cudaGetSymbolAddress((void**)&Vtlo, g_Vtlo);
    cudaGetSymbolAddress((void**)&AOhi, g_AOhi);
    cudaGetSymbolAddress((void**)&AOlo, g_AOlo);

    convert_split<<<512, 256>>>(x, Xhi, Xlo, MM * KK / 4);
    transpose_split4<<<dim3(32, 32, 4), dim3(32, 8)>>>(Wq, Wk, Wv, Wo);

    cudaFuncSetAttribute(gemm_bf16<0>, cudaFuncAttributeMaxDynamicSharedMemorySize, GEMM_SMEM);
    cudaFuncSetAttribute(gemm_bf16<1>, cudaFuncAttributeMaxDynamicSharedMemorySize, GEMM_SMEM);
    cudaFuncSetAttribute(gemm_bf16<2>, cudaFuncAttributeMaxDynamicSharedMemorySize, GEMM_SMEM);
    dim3 gg(NN / 128, MM / 128);
    gemm_bf16<1><<<gg, 256, GEMM_SMEM>>>(Xhi, Xlo, Whi + 0 * (size_t)NN * KK,
                                         Wlo + 0 * (size_t)NN * KK,
                                         nullptr, nullptr, Qhi, Qlo, 0.125f);
    gemm_bf16<1><<<gg, 256, GEMM_SMEM>>>(Xhi, Xlo, Whi + 1 * (size_t)NN * KK,
                                         Wlo + 1 * (size_t)NN * KK,
                                         nullptr, nullptr, Khi, Klo, 1.0f);
    gemm_bf16<2><<<gg, 256, GEMM_SMEM>>>(Xhi, Xlo, Whi + 2 * (size_t)NN * KK,
                                         Wlo + 2 * (size_t)NN * KK,
                                         nullptr, nullptr, Vthi, Vtlo, 1.0f);

    cudaFuncSetAttribute(flash_tc, cudaFuncAttributeMaxDynamicSharedMemorySize, FLASH_SMEM);
    flash_tc<<<dim3(SEQ / 64, BATCH * NHEAD), 128, FLASH_SMEM>>>(
        Qhi, Qlo, Khi, Klo, Vthi, Vtlo, AOhi, AOlo);

    gemm_bf16<0><<<gg, 256, GEMM_SMEM>>>(AOhi, AOlo, Whi + 3 * (size_t)NN * KK,
                                         Wlo + 3 * (size_t)NN * KK,
                                         out, bo, nullptr, nullptr, 1.0f);
}

// round 6
// speedup vs baseline: 2.5760x; 1.0021x over previous
#include <cuda_runtime.h>
#include <cuda_bf16.h>
#include <math.h>
#include <stdint.h>

// Fixed problem shape
#define BATCH 4
#define SEQ   2048
#define DMODEL 1024
#define NHEAD 16
#define HD    64
#define MM (BATCH*SEQ)     // 8192
#define KK DMODEL          // 1024
#define NN DMODEL          // 1024

// bf16 split operands (device globals; no allocation allowed)
__device__ __nv_bfloat16 g_Xhi[MM*KK];
__device__ __nv_bfloat16 g_Xlo[MM*KK];
__device__ __nv_bfloat16 g_Whi[4][NN*KK];   // transposed weights [N][K]
__device__ __nv_bfloat16 g_Wlo[4][NN*KK];
__device__ __nv_bfloat16 g_Qhi[MM*NN];      // [b*SEQ+n][h*64+d], pre-scaled 0.125
__device__ __nv_bfloat16 g_Qlo[MM*NN];
__device__ __nv_bfloat16 g_Khi[MM*NN];
__device__ __nv_bfloat16 g_Klo[MM*NN];
__device__ __nv_bfloat16 g_Vthi[MM*NN];     // [(b*16+h)*64+d][key]  (transposed)
__device__ __nv_bfloat16 g_Vtlo[MM*NN];
__device__ __nv_bfloat16 g_AOhi[MM*NN];
__device__ __nv_bfloat16 g_AOlo[MM*NN];

// ---------------------------------------------------------------------------
__device__ __forceinline__ uint32_t smem_u32(const void* p) {
    uint32_t a;
    asm("{ .reg .u64 t; cvta.to.shared.u64 t, %1; cvt.u32.u64 %0, t; }"
        : "=r"(a) : "l"(p));
    return a;
}
__device__ __forceinline__ void cp_async16(uint32_t dst, const void* src) {
    asm volatile("cp.async.cg.shared.global [%0], [%1], 16;"
                 :: "r"(dst), "l"(src) : "memory");
}
__device__ __forceinline__ void mma_bf16(float* d, const uint32_t* a,
                                         uint32_t b0, uint32_t b1) {
    asm volatile(
        "mma.sync.aligned.m16n8k16.row.col.f32.bf16.bf16.f32 "
        "{%0,%1,%2,%3}, {%4,%5,%6,%7}, {%8,%9}, {%0,%1,%2,%3};"
        : "+f"(d[0]), "+f"(d[1]), "+f"(d[2]), "+f"(d[3])
        : "r"(a[0]), "r"(a[1]), "r"(a[2]), "r"(a[3]), "r"(b0), "r"(b1));
}
__device__ __forceinline__ void split_bf16(float x, __nv_bfloat16& h, __nv_bfloat16& l) {
    h = __float2bfloat16_rn(x);
    l = __float2bfloat16_rn(x - __bfloat162float(h));
}
__device__ __forceinline__ void split_pack2(float f0, float f1,
                                            uint32_t& hp, uint32_t& lp) {
    __nv_bfloat16 h0, l0, h1, l1;
    split_bf16(f0, h0, l0);
    split_bf16(f1, h1, l1);
    hp = ((uint32_t)*(uint16_t*)&h1 << 16) | *(uint16_t*)&h0;
    lp = ((uint32_t)*(uint16_t*)&l1 << 16) | *(uint16_t*)&l0;
}

// ---------------------------------------------------------------------------
// Convert fp32 -> bf16 hi/lo (grid-stride, float4)
// ---------------------------------------------------------------------------
__global__ __launch_bounds__(256) void convert_split(
    const float* __restrict__ src, __nv_bfloat16* __restrict__ hi,
    __nv_bfloat16* __restrict__ lo, int n4)
{
    int idx = blockIdx.x * blockDim.x + threadIdx.x;
    int stride = gridDim.x * blockDim.x;
    for (int i = idx; i < n4; i += stride) {
        float4 v = ((const float4*)src)[i];
        __nv_bfloat16 h[4], l[4];
        split_bf16(v.x, h[0], l[0]);
        split_bf16(v.y, h[1], l[1]);
        split_bf16(v.z, h[2], l[2]);
        split_bf16(v.w, h[3], l[3]);
        ((uint2*)hi)[i] = *(uint2*)h;
        ((uint2*)lo)[i] = *(uint2*)l;
    }
}

// ---------------------------------------------------------------------------
// Transpose + split 4 weights: W[K][N] fp32 -> WT hi/lo [N][K] bf16
// ---------------------------------------------------------------------------
__global__ __launch_bounds__(256) void transpose_split4(
    const float* __restrict__ s0, const float* __restrict__ s1,
    const float* __restrict__ s2, const float* __restrict__ s3)
{
    const float* s;
    __nv_bfloat16 *dh, *dl;
    switch (blockIdx.z) {
        case 0: s = s0; dh = g_Whi[0]; dl = g_Wlo[0]; break;
        case 1: s = s1; dh = g_Whi[1]; dl = g_Wlo[1]; break;
        case 2: s = s2; dh = g_Whi[2]; dl = g_Wlo[2]; break;
        default: s = s3; dh = g_Whi[3]; dl = g_Wlo[3]; break;
    }
    __shared__ float t[32][33];
    int x0 = blockIdx.x * 32, y0 = blockIdx.y * 32;
    int tx = threadIdx.x, ty = threadIdx.y;
#pragma unroll
    for (int j = 0; j < 4; j++)
        t[ty + j * 8][tx] = s[(size_t)(y0 + ty + j * 8) * NN + x0 + tx];
    __syncthreads();
#pragma unroll
    for (int j = 0; j < 4; j++) {
        float v = t[tx][ty + j * 8];
        __nv_bfloat16 h, l;
        split_bf16(v, h, l);
        size_t o = (size_t)(x0 + ty + j * 8) * KK + y0 + tx;
        dh[o] = h;
        dl[o] = l;
    }
}

// ---------------------------------------------------------------------------
// bf16-split GEMM via mma.sync. Term-major MMA issue (RAW distance 16).
// MODE: 0 = fp32 out + bias; 1 = bf16 hi/lo out scaled; 2 = bf16 transposed V.
// ---------------------------------------------------------------------------
#define BKC 64
#define NCHUNKS (KK / BKC)            // 16
#define ROWB 144
#define ARR_BYTES (128 * ROWB)
#define STAGE_BYTES (4 * ARR_BYTES)
#define GEMM_SMEM (2 * STAGE_BYTES)   // 147456

template <int MODE>
__global__ __launch_bounds__(256, 1) void gemm_bf16(
    const __nv_bfloat16* __restrict__ Ahi, const __nv_bfloat16* __restrict__ Alo,
    const __nv_bfloat16* __restrict__ Bhi, const __nv_bfloat16* __restrict__ Blo,
    float* __restrict__ C, const float* __restrict__ bias,
    __nv_bfloat16* __restrict__ Ohi, __nv_bfloat16* __restrict__ Olo,
    float scale)
{
    extern __shared__ __align__(16) char smb[];
    const uint32_t sbase = smem_u32(smb);
    const int tid = threadIdx.x;
    const int wid = tid >> 5;
    const int l = tid & 31;
    const int wm = wid & 3;
    const int wn = wid >> 2;
    const int m0 = blockIdx.y * 128;
    const int n0 = blockIdx.x * 128;

    float acc[2][8][4];
#pragma unroll
    for (int f = 0; f < 2; f++)
#pragma unroll
        for (int g = 0; g < 8; g++)
#pragma unroll
            for (int r = 0; r < 4; r++) acc[f][g][r] = 0.0f;

    auto issue = [&](int c) {
        const int kc0 = c * BKC;
        const uint32_t sb = sbase + (c & 1) * STAGE_BYTES;
#pragma unroll
        for (int i = 0; i < 16; i++) {
            int id = tid + i * 256;
            int arr = id >> 10;
            int rc = id & 1023;
            int row = rc >> 3;
            const __nv_bfloat16* gp;
            int grow;
            if (arr == 0)      { gp = Ahi; grow = m0 + row; }
            else if (arr == 1) { gp = Alo; grow = m0 + row; }
            else if (arr == 2) { gp = Bhi; grow = n0 + row; }
            else               { gp = Blo; grow = n0 + row; }
            const void* src = gp + (size_t)grow * KK + kc0 + (rc & 7) * 8;
            uint32_t dst = sb + arr * ARR_BYTES + row * ROWB + (rc & 7) * 16;
            cp_async16(dst, src);
        }
    };

    issue(0);
    asm volatile("cp.async.commit_group;" ::: "memory");

    const int lr = l >> 2;
    const int lc = (l & 3) * 2;

    for (int c = 0; c < NCHUNKS; c++) {
        if (c + 1 < NCHUNKS) {
            issue(c + 1);
            asm volatile("cp.async.commit_group;" ::: "memory");
            asm volatile("cp.async.wait_group 1;" ::: "memory");
        } else {
            asm volatile("cp.async.wait_group 0;" ::: "memory");
        }
        __syncthreads();

        const char* sb = smb + (c & 1) * STAGE_BYTES;
#pragma unroll
        for (int ks = 0; ks < 4; ks++) {
            const int kc = ks * 16 + lc;
            uint32_t ahi[2][4], alo[2][4];
#pragma unroll
            for (int f = 0; f < 2; f++) {
                int rowA = wm * 32 + f * 16 + lr;
                const char* pa = sb + rowA * ROWB + kc * 2;
                ahi[f][0] = *(const uint32_t*)(pa);
                ahi[f][1] = *(const uint32_t*)(pa + 8 * ROWB);
                ahi[f][2] = *(const uint32_t*)(pa + 16);
                ahi[f][3] = *(const uint32_t*)(pa + 8 * ROWB + 16);
                const char* pl = pa + ARR_BYTES;
                alo[f][0] = *(const uint32_t*)(pl);
                alo[f][1] = *(const uint32_t*)(pl + 8 * ROWB);
                alo[f][2] = *(const uint32_t*)(pl + 16);
                alo[f][3] = *(const uint32_t*)(pl + 8 * ROWB + 16);
            }
            // hoist all B fragments (8 n-groups, hi+lo)
            uint32_t bh0[8], bh1[8], bl0[8], bl1[8];
#pragma unroll
            for (int g = 0; g < 8; g++) {
                int rowBn = wn * 64 + g * 8 + lr;
                const char* pb = sb + 2 * ARR_BYTES + rowBn * ROWB + kc * 2;
                bh0[g] = *(const uint32_t*)(pb);
                bh1[g] = *(const uint32_t*)(pb + 16);
                bl0[g] = *(const uint32_t*)(pb + ARR_BYTES);
                bl1[g] = *(const uint32_t*)(pb + ARR_BYTES + 16);
            }
            // term-major: same-acc reuse distance = 16 MMAs
#pragma unroll
            for (int g = 0; g < 8; g++)
#pragma unroll
                for (int f = 0; f < 2; f++)
                    mma_bf16(acc[f][g], ahi[f], bh0[g], bh1[g]);
#pragma unroll
            for (int g = 0; g < 8; g++)
#pragma unroll
                for (int f = 0; f < 2; f++)
                    mma_bf16(acc[f][g], ahi[f], bl0[g], bl1[g]);
#pragma unroll
            for (int g = 0; g < 8; g++)
#pragma unroll
                for (int f = 0; f < 2; f++)
                    mma_bf16(acc[f][g], alo[f], bh0[g], bh1[g]);
        }
        __syncthreads();
    }

    // Epilogue
#pragma unroll
    for (int f = 0; f < 2; f++) {
        int r0 = m0 + wm * 32 + f * 16 + lr;
#pragma unroll
        for (int g = 0; g < 8; g++) {
            int cc = n0 + wn * 64 + g * 8 + lc;
            if (MODE == 0) {
                float bx = bias[cc], by = bias[cc + 1];
                float2 v0 = make_float2(acc[f][g][0] + bx, acc[f][g][1] + by);
                float2 v1 = make_float2(acc[f][g][2] + bx, acc[f][g][3] + by);
                *(float2*)(C + (size_t)r0 * NN + cc) = v0;
                *(float2*)(C + (size_t)(r0 + 8) * NN + cc) = v1;
            } else if (MODE == 1) {
                uint32_t hp, lp;
                split_pack2(acc[f][g][0] * scale, acc[f][g][1] * scale, hp, lp);
                *(uint32_t*)(Ohi + (size_t)r0 * NN + cc) = hp;
                *(uint32_t*)(Olo + (size_t)r0 * NN + cc) = lp;
                split_pack2(acc[f][g][2] * scale, acc[f][g][3] * scale, hp, lp);
                *(uint32_t*)(Ohi + (size_t)(r0 + 8) * NN + cc) = hp;
                *(uint32_t*)(Olo + (size_t)(r0 + 8) * NN + cc) = lp;
            } else {
#pragma unroll
                for (int rr = 0; rr < 2; rr++) {
                    int row = r0 + rr * 8;
                    int b = row >> 11, n = row & 2047;
#pragma unroll
                    for (int cj = 0; cj < 2; cj++) {
                        int col = cc + cj;
                        float v = acc[f][g][rr * 2 + cj];
                        __nv_bfloat16 h, lo2;
                        split_bf16(v, h, lo2);
                        size_t o = ((size_t)(b * 16) * 64 + col) * SEQ + n;
                        Ohi[o] = h;
                        Olo[o] = lo2;
                    }
                }
            }
        }
    }
}

// ---------------------------------------------------------------------------
// Tensor-core flash attention (causal), bf16 3-term split, term-major issue.
// ---------------------------------------------------------------------------
#define FQ_HI 0
#define FQ_LO 9216
#define FK_BASE 18432
#define FV_BASE 55296
#define FP_HI 92160
#define FP_LO 101376
#define FLASH_SMEM 110592

__global__ __launch_bounds__(128, 2) void flash_tc(
    const __nv_bfloat16* __restrict__ Qhi, const __nv_bfloat16* __restrict__ Qlo,
    const __nv_bfloat16* __restrict__ Khi, const __nv_bfloat16* __restrict__ Klo,
    const __nv_bfloat16* __restrict__ Vthi, const __nv_bfloat16* __restrict__ Vtlo,
    __nv_bfloat16* __restrict__ AOhi, __nv_bfloat16* __restrict__ AOlo)
{
    extern __shared__ __align__(16) char smf[];
    const uint32_t sb = smem_u32(smf);
    const int tid = threadIdx.x;
    const int w = tid >> 5;
    const int l = tid & 31;
    const int lr = l >> 2;
    const int lq = l & 3;
    const int ib = gridDim.x - 1 - blockIdx.x;
    const int bh = blockIdx.y;
    const int b = bh >> 4;
    const int h = bh & 15;
    const int i0 = ib * 64;
    const size_t qrow0 = (size_t)b * SEQ + i0;

    // ---- load Q (hi+lo) ----
#pragma unroll
    for (int i = 0; i < 8; i++) {
        int id = tid + i * 128;
        int arr = id >> 9;
        int rc = id & 511;
        int row = rc >> 3, ch = rc & 7;
        const __nv_bfloat16* gp = arr ? Qlo : Qhi;
        cp_async16(sb + arr * 9216 + row * 144 + ch * 16,
                   gp + (qrow0 + row) * DMODEL + h * 64 + ch * 8);
    }

    auto issueKV = [&](int jb) {
        const int s = jb & 1;
        const int j0 = jb * 64;
#pragma unroll
        for (int i = 0; i < 16; i++) {
            int id = tid + i * 128;
            int half = id >> 10;
            int rc = id & 1023;
            int arr = rc >> 9;
            int r2 = rc & 511;
            int row = r2 >> 3, ch = r2 & 7;
            const __nv_bfloat16* gp;
            const void* src;
            uint32_t dst;
            if (half == 0) {
                gp = arr ? Klo : Khi;
                src = gp + ((size_t)b * SEQ + j0 + row) * DMODEL + h * 64 + ch * 8;
                dst = sb + FK_BASE + s * 18432 + arr * 9216 + row * 144 + ch * 16;
            } else {
                gp = arr ? Vtlo : Vthi;
                src = gp + ((size_t)bh * 64 + row) * SEQ + j0 + ch * 8;
                dst = sb + FV_BASE + s * 18432 + arr * 9216 + row * 144 + ch * 16;
            }
            cp_async16(dst, src);
        }
    };

    issueKV(0);
    asm volatile("cp.async.commit_group;" ::: "memory");

    float mrow[2] = {-1e30f, -1e30f};
    float lsum[2] = {0.0f, 0.0f};
    float oacc[8][4];
#pragma unroll
    for (int g = 0; g < 8; g++)
#pragma unroll
        for (int r = 0; r < 4; r++) oacc[g][r] = 0.0f;

    for (int jb = 0; jb <= ib; jb++) {
        const int s = jb & 1;
        if (jb < ib) {
            issueKV(jb + 1);
            asm volatile("cp.async.commit_group;" ::: "memory");
            asm volatile("cp.async.wait_group 1;" ::: "memory");
        } else {
            asm volatile("cp.async.wait_group 0;" ::: "memory");
        }
        __syncthreads();

        // ---- S = Q @ K^T (term-major) ----
        float sacc[8][4];
#pragma unroll
        for (int g = 0; g < 8; g++)
#pragma unroll
            for (int r = 0; r < 4; r++) sacc[g][r] = 0.0f;

        const char* qh = smf;
        const char* kb = smf + FK_BASE + s * 18432;
#pragma unroll
        for (int ks = 0; ks < 4; ks++) {
            const int kc = ks * 32 + lq * 4;
            uint32_t ahi[4], alo[4];
            {
                const char* pa = qh + (w * 16 + lr) * 144 + kc;
                ahi[0] = *(const uint32_t*)(pa);
                ahi[1] = *(const uint32_t*)(pa + 8 * 144);
                ahi[2] = *(const uint32_t*)(pa + 16);
                ahi[3] = *(const uint32_t*)(pa + 8 * 144 + 16);
                const char* pl = pa + 9216;
                alo[0] = *(const uint32_t*)(pl);
                alo[1] = *(const uint32_t*)(pl + 8 * 144);
                alo[2] = *(const uint32_t*)(pl + 16);
                alo[3] = *(const uint32_t*)(pl + 8 * 144 + 16);
            }
            uint32_t bh0[8], bh1[8], bl0[8], bl1[8];
#pragma unroll
            for (int g = 0; g < 8; g++) {
                const char* pb = kb + (g * 8 + lr) * 144 + kc;
                bh0[g] = *(const uint32_t*)(pb);
                bh1[g] = *(const uint32_t*)(pb + 16);
                bl0[g] = *(const uint32_t*)(pb + 9216);
                bl1[g] = *(const uint32_t*)(pb + 9216 + 16);
            }
#pragma unroll
            for (int g = 0; g < 8; g++) mma_bf16(sacc[g], ahi, bh0[g], bh1[g]);
#pragma unroll
            for (int g = 0; g < 8; g++) mma_bf16(sacc[g], ahi, bl0[g], bl1[g]);
#pragma unroll
            for (int g = 0; g < 8; g++) mma_bf16(sacc[g], alo, bh0[g], bh1[g]);
        }

        // ---- causal mask on diagonal block ----
        if (jb == ib) {
#pragma unroll
            for (int g = 0; g < 8; g++)
#pragma unroll
                for (int r = 0; r < 4; r++) {
                    int rowL = w * 16 + lr + (r >> 1) * 8;
                    int colL = g * 8 + lq * 2 + (r & 1);
                    if (colL > rowL) sacc[g][r] = -1e30f;
                }
        }

        // ---- online softmax + P split to smem ----
#pragma unroll
        for (int ri = 0; ri < 2; ri++) {
            const int c0 = ri * 2;
            float rmax = -1e30f;
#pragma unroll
            for (int g = 0; g < 8; g++)
                rmax = fmaxf(rmax, fmaxf(sacc[g][c0], sacc[g][c0 + 1]));
            rmax = fmaxf(rmax, __shfl_xor_sync(0xffffffffu, rmax, 1));
            rmax = fmaxf(rmax, __shfl_xor_sync(0xffffffffu, rmax, 2));
            float mnew = fmaxf(mrow[ri], rmax);
            float alpha = __expf(mrow[ri] - mnew);
            float rsum = 0.0f;
            const int prow = w * 16 + lr + ri * 8;
#pragma unroll
            for (int g = 0; g < 8; g++) {
                float p0 = __expf(sacc[g][c0] - mnew);
                float p1 = __expf(sacc[g][c0 + 1] - mnew);
                rsum += p0 + p1;
                uint32_t hp, lp;
                split_pack2(p0, p1, hp, lp);
                int boff = prow * 144 + (g * 8 + lq * 2) * 2;
                *(uint32_t*)(smf + FP_HI + boff) = hp;
                *(uint32_t*)(smf + FP_LO + boff) = lp;
            }
            rsum += __shfl_xor_sync(0xffffffffu, rsum, 1);
            rsum += __shfl_xor_sync(0xffffffffu, rsum, 2);
            lsum[ri] = lsum[ri] * alpha + rsum;
            mrow[ri] = mnew;
#pragma unroll
            for (int g = 0; g < 8; g++) {
                oacc[g][c0] *= alpha;
                oacc[g][c0 + 1] *= alpha;
            }
        }
        __syncwarp();

        // ---- O += P @ V (term-major) ----
        const char* vb = smf + FV_BASE + s * 18432;
#pragma unroll
        for (int ks = 0; ks < 4; ks++) {
            const int kc = ks * 32 + lq * 4;
            uint32_t phi[4], plo[4];
            {
                const char* pa = smf + FP_HI + (w * 16 + lr) * 144 + kc;
                phi[0] = *(const uint32_t*)(pa);
                phi[1] = *(const uint32_t*)(pa + 8 * 144);
                phi[2] = *(const uint32_t*)(pa + 16);
                phi[3] = *(const uint32_t*)(pa + 8 * 144 + 16);
                const char* pl = smf + FP_LO + (w * 16 + lr) * 144 + kc;
                plo[0] = *(const uint32_t*)(pl);
                plo[1] = *(const uint32_t*)(pl + 8 * 144);
                plo[2] = *(const uint32_t*)(pl + 16);
                plo[3] = *(const uint32_t*)(pl + 8 * 144 + 16);
            }
            uint32_t bh0[8], bh1[8], bl0[8], bl1[8];
#pragma unroll
            for (int g = 0; g < 8; g++) {
                const char* pb = vb + (g * 8 + lr) * 144 + kc;
                bh0[g] = *(const uint32_t*)(pb);
                bh1[g] = *(const uint32_t*)(pb + 16);
                bl0[g] = *(const uint32_t*)(pb + 9216);
                bl1[g] = *(const uint32_t*)(pb + 9216 + 16);
            }
#pragma unroll
            for (int g = 0; g < 8; g++) mma_bf16(oacc[g], phi, bh0[g], bh1[g]);
#pragma unroll
            for (int g = 0; g < 8; g++) mma_bf16(oacc[g], phi, bl0[g], bl1[g]);
#pragma unroll
            for (int g = 0; g < 8; g++) mma_bf16(oacc[g], plo, bh0[g], bh1[g]);
        }
        __syncthreads();
    }

    // ---- epilogue: AO = O / l -> bf16 hi/lo ----
#pragma unroll
    for (int ri = 0; ri < 2; ri++) {
        float inv = 1.0f / lsum[ri];
        size_t grow = qrow0 + w * 16 + lr + ri * 8;
#pragma unroll
        for (int g = 0; g < 8; g++) {
            int col = h * 64 + g * 8 + lq * 2;
            uint32_t hp, lp;
            split_pack2(oacc[g][ri * 2] * inv, oacc[g][ri * 2 + 1] * inv, hp, lp);
            *(uint32_t*)(AOhi + grow * DMODEL + col) = hp;
            *(uint32_t*)(AOlo + grow * DMODEL + col) = lp;
        }
    }
}

// ---------------------------------------------------------------------------
extern "C" void kernel_launch(void* const* d_in, const int* in_sizes, int n_in,
                              void* d_out, int out_size)
{
    (void)in_sizes; (void)n_in; (void)out_size;
    const float* x  = (const float*)d_in[0];
    const float* Wq = (const float*)d_in[1];
    const float* Wk = (const float*)d_in[2];
    const float* Wv = (const float*)d_in[3];
    const float* Wo = (const float*)d_in[4];
    const float* bo = (const float*)d_in[5];
    float* out = (float*)d_out;

    __nv_bfloat16 *Xhi, *Xlo, *Whi, *Wlo, *Qhi, *Qlo, *Khi, *Klo,
                  *Vthi, *Vtlo, *AOhi, *AOlo;
    cudaGetSymbolAddress((void**)&Xhi,  g_Xhi);
    cudaGetSymbolAddress((void**)&Xlo,  g_Xlo);
    cudaGetSymbolAddress((void**)&Whi,  g_Whi);
    cudaGetSymbolAddress((void**)&Wlo,  g_Wlo);
    cudaGetSymbolAddress((void**)&Qhi,  g_Qhi);
    cudaGetSymbolAddress((void**)&Qlo,  g_Qlo);
    cudaGetSymbolAddress((void**)&Khi,  g_Khi);
    cudaGetSymbolAddress((void**)&Klo,  g_Klo);
    cudaGetSymbolAddress((void**)&Vthi, g_Vthi);
    cudaGetSymbolAddress((void**)&Vtlo, g_Vtlo);
    cudaGetSymbolAddress((void**)&AOhi, g_AOhi);
    cudaGetSymbolAddress((void**)&AOlo, g_AOlo);

    convert_split<<<512, 256>>>(x, Xhi, Xlo, MM * KK / 4);
    transpose_split4<<<dim3(32, 32, 4), dim3(32, 8)>>>(Wq, Wk, Wv, Wo);

    cudaFuncSetAttribute(gemm_bf16<0>, cudaFuncAttributeMaxDynamicSharedMemorySize, GEMM_SMEM);
    cudaFuncSetAttribute(gemm_bf16<1>, cudaFuncAttributeMaxDynamicSharedMemorySize, GEMM_SMEM);
    cudaFuncSetAttribute(gemm_bf16<2>, cudaFuncAttributeMaxDynamicSharedMemorySize, GEMM_SMEM);
    dim3 gg(NN / 128, MM / 128);
    gemm_bf16<1><<<gg, 256, GEMM_SMEM>>>(Xhi, Xlo, Whi + 0 * (size_t)NN * KK,
                                         Wlo + 0 * (size_t)NN * KK,
                                         nullptr, nullptr, Qhi, Qlo, 0.125f);
    gemm_bf16<1><<<gg, 256, GEMM_SMEM>>>(Xhi, Xlo, Whi + 1 * (size_t)NN * KK,
                                         Wlo + 1 * (size_t)NN * KK,
                                         nullptr, nullptr, Khi, Klo, 1.0f);
    gemm_bf16<2><<<gg, 256, GEMM_SMEM>>>(Xhi, Xlo, Whi + 2 * (size_t)NN * KK,
                                         Wlo + 2 * (size_t)NN * KK,
                                         nullptr, nullptr, Vthi, Vtlo, 1.0f);

    cudaFuncSetAttribute(flash_tc, cudaFuncAttributeMaxDynamicSharedMemorySize, FLASH_SMEM);
    flash_tc<<<dim3(SEQ / 64, BATCH * NHEAD), 128, FLASH_SMEM>>>(
        Qhi, Qlo, Khi, Klo, Vthi, Vtlo, AOhi, AOlo);

    gemm_bf16<0><<<gg, 256, GEMM_SMEM>>>(AOhi, AOlo, Whi + 3 * (size_t)NN * KK,
                                         Wlo + 3 * (size_t)NN * KK,
                                         out, bo, nullptr, nullptr, 1.0f);
}